// round 3
// baseline (speedup 1.0000x reference)
#include <cuda_runtime.h>

// SimpleRNN: B=1024, T=2048, I=1, H=64, O=1
// 2 batch rows per warp (independent streams -> ILP), weights shared in regs.
// 128 CTAs x 4 warps x 2 rows. Lane L owns h[2L],h[2L+1] of each row.
// fma.rn.f32x2 K-packed dot products, 4 chains per output, h in smem
// (double-buffered), y staged in padded smem and reduced every 32 steps.

#define BB 1024
#define TT 2048
#define HH 64
#define WARPS_PER_CTA 4
#define ROWS 2
#define THREADS (32 * WARPS_PER_CTA)

typedef unsigned long long u64;

__device__ __forceinline__ u64 fma2(u64 a, u64 b, u64 c) {
    u64 d;
    asm("fma.rn.f32x2 %0, %1, %2, %3;" : "=l"(d) : "l"(a), "l"(b), "l"(c));
    return d;
}
__device__ __forceinline__ u64 pack2(float lo, float hi) {
    u64 r;
    asm("mov.b64 %0, {%1, %2};" : "=l"(r) : "f"(lo), "f"(hi));
    return r;
}
__device__ __forceinline__ void unpack2(u64 v, float& lo, float& hi) {
    asm("mov.b64 {%0, %1}, %2;" : "=f"(lo), "=f"(hi) : "l"(v));
}
__device__ __forceinline__ float tanh_fast(float x) {
    float y;
    asm("tanh.approx.f32 %0, %1;" : "=f"(y) : "f"(x));
    return y;
}

__global__ void __launch_bounds__(THREADS)
rnn_2rows(const float* __restrict__ x_seq,   // [B, T]
          const float* __restrict__ W_h,     // [H, H]
          const float* __restrict__ W_x,     // [H, 1]
          const float* __restrict__ W_y,     // [1, H]
          float* __restrict__ out)           // [B, T]
{
    __shared__ float hbuf[2][WARPS_PER_CTA][ROWS][HH];      // 4 KB
    __shared__ float pbuf[WARPS_PER_CTA][ROWS][32][33];     // 33.8 KB

    const int warp = threadIdx.x >> 5;
    const int lane = threadIdx.x & 31;
    const int b0 = (blockIdx.x * WARPS_PER_CTA + warp) * ROWS;

    const int j0 = 2 * lane;
    const int j1 = 2 * lane + 1;

    // ---- Weights into registers (shared by both rows) ----
    u64 wh0[HH / 2], wh1[HH / 2];
    const float2* Wh2 = reinterpret_cast<const float2*>(W_h);
#pragma unroll
    for (int k = 0; k < HH / 2; ++k) {
        float2 a = Wh2[j0 * (HH / 2) + k];
        float2 c = Wh2[j1 * (HH / 2) + k];
        wh0[k] = pack2(a.x, a.y);
        wh1[k] = pack2(c.x, c.y);
    }
    const float wx0 = W_x[j0], wx1 = W_x[j1];
    const float wy0 = W_y[j0], wy1 = W_y[j1];

    // ---- h = 0 ----
#pragma unroll
    for (int r = 0; r < ROWS; ++r)
        reinterpret_cast<float2*>(hbuf[0][warp][r])[lane] =
            make_float2(0.f, 0.f);
    __syncwarp();

    const float* xp[ROWS];
    float* op[ROWS];
    float xv[ROWS];
#pragma unroll
    for (int r = 0; r < ROWS; ++r) {
        xp[r] = x_seq + (long)(b0 + r) * TT;
        op[r] = out + (long)(b0 + r) * TT;
        xv[r] = xp[r][lane];
    }
    int cur = 0;

    for (int t0 = 0; t0 < TT; t0 += 32) {
        float xnext[ROWS];
#pragma unroll
        for (int r = 0; r < ROWS; ++r)
            xnext[r] = (t0 + 32 < TT) ? xp[r][t0 + 32 + lane] : 0.f;

        for (int s = 0; s < 32; ++s) {
            float xs[ROWS];
#pragma unroll
            for (int r = 0; r < ROWS; ++r)
                xs[r] = __shfl_sync(0xffffffffu, xv[r], s);

            // 4 chains per output per row, 8 deep each.
            u64 a0a[ROWS], a0b[ROWS], a1a[ROWS], a1b[ROWS];
#pragma unroll
            for (int r = 0; r < ROWS; ++r) {
                a0a[r] = pack2(xs[r] * wx0, 0.f);
                a0b[r] = 0ull;
                a1a[r] = pack2(xs[r] * wx1, 0.f);
                a1b[r] = 0ull;
            }
#pragma unroll
            for (int k = 0; k < HH / 8; ++k) {  // 8 iters
#pragma unroll
                for (int r = 0; r < ROWS; ++r) {
                    const ulonglong2* hc =
                        reinterpret_cast<const ulonglong2*>(hbuf[cur][warp][r]);
                    ulonglong2 qa = hc[2 * k];
                    ulonglong2 qb = hc[2 * k + 1];
                    a0a[r] = fma2(qa.x, wh0[4 * k],     a0a[r]);
                    a0a[r] = fma2(qa.y, wh0[4 * k + 1], a0a[r]);
                    a1a[r] = fma2(qa.x, wh1[4 * k],     a1a[r]);
                    a1a[r] = fma2(qa.y, wh1[4 * k + 1], a1a[r]);
                    a0b[r] = fma2(qb.x, wh0[4 * k + 2], a0b[r]);
                    a0b[r] = fma2(qb.y, wh0[4 * k + 3], a0b[r]);
                    a1b[r] = fma2(qb.x, wh1[4 * k + 2], a1b[r]);
                    a1b[r] = fma2(qb.y, wh1[4 * k + 3], a1b[r]);
                }
            }
            const int nxt = cur ^ 1;
#pragma unroll
            for (int r = 0; r < ROWS; ++r) {
                float p0, p1, q0, q1, u0, u1, v0, v1;
                unpack2(a0a[r], p0, p1);
                unpack2(a0b[r], q0, q1);
                unpack2(a1a[r], u0, u1);
                unpack2(a1b[r], v0, v1);
                const float h0 = tanh_fast((p0 + p1) + (q0 + q1));
                const float h1 = tanh_fast((u0 + u1) + (v0 + v1));
                reinterpret_cast<float2*>(hbuf[nxt][warp][r])[lane] =
                    make_float2(h0, h1);
                pbuf[warp][r][s][lane] = fmaf(h0, wy0, h1 * wy1);
            }
            __syncwarp();
            cur = nxt;
        }

        // y[t0+L] = sum over lanes of pbuf[r][L][*]; stride-33 conflict-free.
#pragma unroll
        for (int r = 0; r < ROWS; ++r) {
            float s0 = 0.f, s1 = 0.f, s2 = 0.f, s3 = 0.f;
#pragma unroll
            for (int i = 0; i < 32; i += 4) {
                s0 += pbuf[warp][r][lane][i];
                s1 += pbuf[warp][r][lane][i + 1];
                s2 += pbuf[warp][r][lane][i + 2];
                s3 += pbuf[warp][r][lane][i + 3];
            }
            op[r][t0 + lane] = (s0 + s1) + (s2 + s3);
            xv[r] = xnext[r];
        }
        __syncwarp();
    }
}

extern "C" void kernel_launch(void* const* d_in, const int* in_sizes, int n_in,
                              void* d_out, int out_size) {
    const float* x_seq = (const float*)d_in[0];  // [1024, 2048, 1]
    const float* W_h   = (const float*)d_in[1];  // [64, 64]
    const float* W_x   = (const float*)d_in[2];  // [64, 1]
    const float* W_y   = (const float*)d_in[3];  // [1, 64]
    float* out = (float*)d_out;                  // [1024, 2048, 1]

    const int blocks = BB / (WARPS_PER_CTA * ROWS);  // 128
    rnn_2rows<<<blocks, THREADS>>>(x_seq, W_h, W_x, W_y, out);
}

// round 4
// speedup vs baseline: 1.5310x; 1.5310x over previous
#include <cuda_runtime.h>

// SimpleRNN: B=1024, T=2048, I=1, H=64, O=1
// Row split across 2 warps: 64 lanes per batch row, lane owns ONE hidden unit.
// => 2048 warps total = 4 warps/SMSP on 128 SMs (256 CTAs x 8 warps, 2 CTAs/SM)
// fma.rn.f32x2 K-packed dot products (32 fma2/lane/step, 4 chains of 8).
// h double-buffered in smem; one __syncthreads per step; y staged in padded
// smem tile and reduced every 32 steps.

#define BB 1024
#define TT 2048
#define HH 64
#define ROWS_PER_CTA 4
#define THREADS 256

typedef unsigned long long u64;

__device__ __forceinline__ u64 fma2(u64 a, u64 b, u64 c) {
    u64 d;
    asm("fma.rn.f32x2 %0, %1, %2, %3;" : "=l"(d) : "l"(a), "l"(b), "l"(c));
    return d;
}
__device__ __forceinline__ u64 pack2(float lo, float hi) {
    u64 r;
    asm("mov.b64 %0, {%1, %2};" : "=l"(r) : "f"(lo), "f"(hi));
    return r;
}
__device__ __forceinline__ void unpack2(u64 v, float& lo, float& hi) {
    asm("mov.b64 {%0, %1}, %2;" : "=f"(lo), "=f"(hi) : "l"(v));
}
__device__ __forceinline__ float tanh_fast(float x) {
    float y;
    asm("tanh.approx.f32 %0, %1;" : "=f"(y) : "f"(x));
    return y;
}

__global__ void __launch_bounds__(THREADS, 2)
rnn_split(const float* __restrict__ x_seq,   // [B, T]
          const float* __restrict__ W_h,     // [H, H]
          const float* __restrict__ W_x,     // [H, 1]
          const float* __restrict__ W_y,     // [1, H]
          float* __restrict__ out)           // [B, T]
{
    __shared__ float hbuf[2][ROWS_PER_CTA][HH];        // 2 KB
    __shared__ float pbuf[ROWS_PER_CTA][32][HH + 1];   // 33.3 KB, padded

    const int warp = threadIdx.x >> 5;
    const int lane = threadIdx.x & 31;
    const int rg   = warp >> 1;          // rowgroup 0..3
    const int half = warp & 1;           // which 32 hidden units
    const int j    = half * 32 + lane;   // owned hidden unit 0..63
    const int row  = blockIdx.x * ROWS_PER_CTA + rg;

    // ---- Weights: W_h row j as 32 packed f32x2 (K-packed) ----
    u64 wh[HH / 2];
    const float2* Wh2 = reinterpret_cast<const float2*>(W_h);
#pragma unroll
    for (int k = 0; k < HH / 2; ++k) {
        float2 a = Wh2[j * (HH / 2) + k];
        wh[k] = pack2(a.x, a.y);
    }
    const float wx = W_x[j];
    const float wy = W_y[j];

    // ---- h = 0 ----
    hbuf[0][rg][j] = 0.f;
    __syncthreads();

    const float* xp = x_seq + (long)row * TT;
    float* op = out + (long)row * TT;

    float xv = xp[lane];  // both warps of the pair load the same 128B window
    int cur = 0;

    for (int t0 = 0; t0 < TT; t0 += 32) {
        const float xnext = (t0 + 32 < TT) ? xp[t0 + 32 + lane] : 0.f;

        for (int s = 0; s < 32; ++s) {
            const float xs = __shfl_sync(0xffffffffu, xv, s);

            const ulonglong2* hc =
                reinterpret_cast<const ulonglong2*>(hbuf[cur][rg]);

            // 4 independent chains, 8 deep; xs*wx folded into init.
            u64 c0 = pack2(xs * wx, 0.f);
            u64 c1 = 0ull, c2 = 0ull, c3 = 0ull;
#pragma unroll
            for (int k = 0; k < HH / 8; ++k) {  // 8 iters, 16B LDS each x2
                ulonglong2 qa = hc[2 * k];       // h[8k..8k+3]
                ulonglong2 qb = hc[2 * k + 1];   // h[8k+4..8k+7]
                c0 = fma2(qa.x, wh[4 * k],     c0);
                c1 = fma2(qa.y, wh[4 * k + 1], c1);
                c2 = fma2(qb.x, wh[4 * k + 2], c2);
                c3 = fma2(qb.y, wh[4 * k + 3], c3);
            }
            float a0, a1, b0, b1, d0, d1, e0, e1;
            unpack2(c0, a0, a1);
            unpack2(c1, b0, b1);
            unpack2(c2, d0, d1);
            unpack2(c3, e0, e1);
            const float h =
                tanh_fast(((a0 + a1) + (b0 + b1)) + ((d0 + d1) + (e0 + e1)));

            const int nxt = cur ^ 1;
            hbuf[nxt][rg][j] = h;
            pbuf[rg][s][j] = h * wy;
            __syncthreads();
            cur = nxt;
        }

        // y[t0+L] = sum_j pbuf[rg][L][j]; warp half 0 of each pair reduces.
        // Stride 65 rows -> lane L reading row L is conflict-free per column.
        if (half == 0) {
            float s0 = 0.f, s1 = 0.f, s2 = 0.f, s3 = 0.f;
#pragma unroll
            for (int i = 0; i < HH; i += 4) {
                s0 += pbuf[rg][lane][i];
                s1 += pbuf[rg][lane][i + 1];
                s2 += pbuf[rg][lane][i + 2];
                s3 += pbuf[rg][lane][i + 3];
            }
            op[t0 + lane] = (s0 + s1) + (s2 + s3);  // coalesced
        }
        __syncthreads();  // pbuf reads done before next block overwrites
        xv = xnext;
    }
}

extern "C" void kernel_launch(void* const* d_in, const int* in_sizes, int n_in,
                              void* d_out, int out_size) {
    const float* x_seq = (const float*)d_in[0];  // [1024, 2048, 1]
    const float* W_h   = (const float*)d_in[1];  // [64, 64]
    const float* W_x   = (const float*)d_in[2];  // [64, 1]
    const float* W_y   = (const float*)d_in[3];  // [1, 64]
    float* out = (float*)d_out;                  // [1024, 2048, 1]

    const int blocks = BB / ROWS_PER_CTA;  // 256 CTAs, 2 per SM on 128 SMs
    rnn_split<<<blocks, THREADS>>>(x_seq, W_h, W_x, W_y, out);
}

// round 5
// speedup vs baseline: 1.7335x; 1.1322x over previous
#include <cuda_runtime.h>

// SimpleRNN: B=1024, T=2048, I=1, H=64, O=1
// One batch row per 64-thread CTA (2 warps). Thread j (0..63) owns hidden
// unit j: 32 fma.rn.f32x2 per step (W_h row j K-packed in registers).
// h exchanged through smem with a 2-warp __syncthreads per step — rows are
// fully independent CTAs, so stalls are hidden by ~7 co-resident CTAs/SM
// across all 148 SMs (~3.5 warps/SMSP). y staged in stride-65 smem tile,
// reduced every 32 steps split across the two warps.

#define BB 1024
#define TT 2048
#define HH 64
#define THREADS 64

typedef unsigned long long u64;

__device__ __forceinline__ u64 fma2(u64 a, u64 b, u64 c) {
    u64 d;
    asm("fma.rn.f32x2 %0, %1, %2, %3;" : "=l"(d) : "l"(a), "l"(b), "l"(c));
    return d;
}
__device__ __forceinline__ u64 pack2(float lo, float hi) {
    u64 r;
    asm("mov.b64 %0, {%1, %2};" : "=l"(r) : "f"(lo), "f"(hi));
    return r;
}
__device__ __forceinline__ void unpack2(u64 v, float& lo, float& hi) {
    asm("mov.b64 {%0, %1}, %2;" : "=f"(lo), "=f"(hi) : "l"(v));
}
__device__ __forceinline__ float tanh_fast(float x) {
    float y;
    asm("tanh.approx.f32 %0, %1;" : "=f"(y) : "f"(x));
    return y;
}

__global__ void __launch_bounds__(THREADS)
rnn_row_cta(const float* __restrict__ x_seq,   // [B, T]
            const float* __restrict__ W_h,     // [H, H]
            const float* __restrict__ W_x,     // [H, 1]
            const float* __restrict__ W_y,     // [1, H]
            float* __restrict__ out)           // [B, T]
{
    __shared__ float hbuf[2][HH];       // double-buffered hidden state
    __shared__ float pbuf[32][65];      // y-partials, stride 65 (bank-free)
    __shared__ float ybuf[32];          // half-1 reduce partials

    const int j    = threadIdx.x;        // owned hidden unit 0..63
    const int lane = j & 31;
    const int half = j >> 5;             // warp 0: units 0..31, warp 1: 32..63
    const int row  = blockIdx.x;

    // ---- W_h row j as 32 packed f32x2 (K-packed) ----
    u64 wh[HH / 2];
    const float2* Wh2 = reinterpret_cast<const float2*>(W_h);
#pragma unroll
    for (int k = 0; k < HH / 2; ++k) {
        float2 a = Wh2[j * (HH / 2) + k];
        wh[k] = pack2(a.x, a.y);
    }
    const float wx = W_x[j];
    const float wy = W_y[j];

    hbuf[0][j] = 0.f;
    __syncthreads();

    const float* xp = x_seq + (long)row * TT;
    float* op = out + (long)row * TT;

    float xv = xp[lane];   // each warp holds the 32-step x window
    int cur = 0;

    for (int t0 = 0; t0 < TT; t0 += 32) {
        const float xnext = (t0 + 32 < TT) ? xp[t0 + 32 + lane] : 0.f;

        for (int s = 0; s < 32; ++s) {
            const float xs = __shfl_sync(0xffffffffu, xv, s);

            const ulonglong2* hc =
                reinterpret_cast<const ulonglong2*>(hbuf[cur]);

            // 4 independent chains, 8 deep; xs*wx folded into init.
            u64 c0 = pack2(xs * wx, 0.f);
            u64 c1 = 0ull, c2 = 0ull, c3 = 0ull;
#pragma unroll
            for (int k = 0; k < HH / 8; ++k) {   // 8 iters
                ulonglong2 qa = hc[2 * k];        // h[8k..8k+3]
                ulonglong2 qb = hc[2 * k + 1];    // h[8k+4..8k+7]
                c0 = fma2(qa.x, wh[4 * k],     c0);
                c1 = fma2(qa.y, wh[4 * k + 1], c1);
                c2 = fma2(qb.x, wh[4 * k + 2], c2);
                c3 = fma2(qb.y, wh[4 * k + 3], c3);
            }
            float a0, a1, b0, b1, d0, d1, e0, e1;
            unpack2(c0, a0, a1);
            unpack2(c1, b0, b1);
            unpack2(c2, d0, d1);
            unpack2(c3, e0, e1);
            const float h =
                tanh_fast(((a0 + a1) + (b0 + b1)) + ((d0 + d1) + (e0 + e1)));

            const int nxt = cur ^ 1;
            hbuf[nxt][j] = h;
            pbuf[s][j] = h * wy;   // bank (65s+j)%32 = (s+j)%32: conflict-free
            __syncthreads();       // only 2 warps — cheap, row-private
            cur = nxt;
        }

        // y[t0+L] = sum_j pbuf[L][j], split between the two warps.
        // Lane L reads row L: bank (65L+i)%32 = (L+i)%32 — conflict-free.
        {
            const int i0 = half * 32;
            float s0 = 0.f, s1 = 0.f, s2 = 0.f, s3 = 0.f;
#pragma unroll
            for (int i = 0; i < 32; i += 4) {
                s0 += pbuf[lane][i0 + i];
                s1 += pbuf[lane][i0 + i + 1];
                s2 += pbuf[lane][i0 + i + 2];
                s3 += pbuf[lane][i0 + i + 3];
            }
            const float part = (s0 + s1) + (s2 + s3);
            if (half == 1) ybuf[lane] = part;
            __syncthreads();
            if (half == 0)
                op[t0 + lane] = part + ybuf[lane];  // coalesced 128B store
        }
        xv = xnext;
    }
}

extern "C" void kernel_launch(void* const* d_in, const int* in_sizes, int n_in,
                              void* d_out, int out_size) {
    const float* x_seq = (const float*)d_in[0];  // [1024, 2048, 1]
    const float* W_h   = (const float*)d_in[1];  // [64, 64]
    const float* W_x   = (const float*)d_in[2];  // [64, 1]
    const float* W_y   = (const float*)d_in[3];  // [1, 64]
    float* out = (float*)d_out;                  // [1024, 2048, 1]

    rnn_row_cta<<<BB, THREADS>>>(x_seq, W_h, W_x, W_y, out);  // 1024 CTAs
}

// round 6
// speedup vs baseline: 2.1143x; 1.2197x over previous
#include <cuda_runtime.h>

// SimpleRNN: B=1024, T=2048, I=1, H=64, O=1
// R2 structure (best: one warp per row, lane owns h[2L],h[2L+1], weights in
// regs, fma.rn.f32x2, h double-buffered in smem) + three changes:
//  1. odd warps start ~160 cyc late (dependent MUFU chain) -> antiphase warp
//     pairs per SMSP so bubbles of one warp are covered by the other's fmas
//  2. packed add.rn.f32x2 reduction tree before tanh (shorter serial tail)
//  3. y-partial STS moved after the barrier (off the h critical path)

#define BB 1024
#define TT 2048
#define HH 64
#define WARPS_PER_CTA 8
#define THREADS (32 * WARPS_PER_CTA)

typedef unsigned long long u64;

__device__ __forceinline__ u64 fma2(u64 a, u64 b, u64 c) {
    u64 d;
    asm("fma.rn.f32x2 %0, %1, %2, %3;" : "=l"(d) : "l"(a), "l"(b), "l"(c));
    return d;
}
__device__ __forceinline__ u64 add2(u64 a, u64 b) {
    u64 d;
    asm("add.rn.f32x2 %0, %1, %2;" : "=l"(d) : "l"(a), "l"(b));
    return d;
}
__device__ __forceinline__ u64 pack2(float lo, float hi) {
    u64 r;
    asm("mov.b64 %0, {%1, %2};" : "=l"(r) : "f"(lo), "f"(hi));
    return r;
}
__device__ __forceinline__ void unpack2(u64 v, float& lo, float& hi) {
    asm("mov.b64 {%0, %1}, %2;" : "=f"(lo), "=f"(hi) : "l"(v));
}
__device__ __forceinline__ float tanh_fast(float x) {
    float y;
    asm("tanh.approx.f32 %0, %1;" : "=f"(y) : "f"(x));
    return y;
}

__global__ void __launch_bounds__(THREADS)
rnn_dephase(const float* __restrict__ x_seq,   // [B, T]
            const float* __restrict__ W_h,     // [H, H]
            const float* __restrict__ W_x,     // [H, 1]
            const float* __restrict__ W_y,     // [1, H]
            float* __restrict__ out)           // [B, T]
{
    __shared__ float hbuf[2][WARPS_PER_CTA][HH];
    __shared__ float pbuf[WARPS_PER_CTA][32][33];

    const int warp = threadIdx.x >> 5;
    const int lane = threadIdx.x & 31;
    const int b = blockIdx.x * WARPS_PER_CTA + warp;

    const int j0 = 2 * lane;
    const int j1 = 2 * lane + 1;

    // ---- Weights into registers ----
    u64 wh0[HH / 2], wh1[HH / 2];
    const float2* Wh2 = reinterpret_cast<const float2*>(W_h);
#pragma unroll
    for (int k = 0; k < HH / 2; ++k) {
        float2 a = Wh2[j0 * (HH / 2) + k];
        float2 c = Wh2[j1 * (HH / 2) + k];
        wh0[k] = pack2(a.x, a.y);
        wh1[k] = pack2(c.x, c.y);
    }
    const float wx0 = W_x[j0], wx1 = W_x[j1];
    const float wy0 = W_y[j0], wy1 = W_y[j1];

    reinterpret_cast<float2*>(hbuf[0][warp])[lane] = make_float2(0.f, 0.f);
    __syncwarp();

    // ---- De-phase: odd warps burn ~160 cyc on a dependent MUFU chain ----
    if (warp & 1) {
        float v = 1.5f + lane;
#pragma unroll
        for (int i = 0; i < 10; ++i)
            asm volatile("rcp.approx.f32 %0, %0;" : "+f"(v));
        if (v == 12345.678f) hbuf[0][warp][lane & 1] = v;  // never taken
    }

    const float* xp = x_seq + (long)b * TT;
    float* op = out + (long)b * TT;

    float xv = xp[lane];
    int cur = 0;

    for (int t0 = 0; t0 < TT; t0 += 32) {
        const float xnext = (t0 + 32 < TT) ? xp[t0 + 32 + lane] : 0.f;

        float yp_prev = 0.f;   // y-partial of previous step (stored post-bar)
        int sp = 0;

#pragma unroll 2
        for (int s = 0; s < 32; ++s) {
            const float xs = __shfl_sync(0xffffffffu, xv, s);

            const ulonglong2* hc =
                reinterpret_cast<const ulonglong2*>(hbuf[cur][warp]);

            u64 acc0a = pack2(xs * wx0, 0.f);
            u64 acc0b = 0ull;
            u64 acc1a = pack2(xs * wx1, 0.f);
            u64 acc1b = 0ull;
#pragma unroll
            for (int k = 0; k < HH / 8; ++k) {  // 8 iters
                ulonglong2 qa = hc[2 * k];
                ulonglong2 qb = hc[2 * k + 1];
                acc0a = fma2(qa.x, wh0[4 * k],     acc0a);
                acc0a = fma2(qa.y, wh0[4 * k + 1], acc0a);
                acc1a = fma2(qa.x, wh1[4 * k],     acc1a);
                acc1a = fma2(qa.y, wh1[4 * k + 1], acc1a);
                acc0b = fma2(qb.x, wh0[4 * k + 2], acc0b);
                acc0b = fma2(qb.y, wh0[4 * k + 3], acc0b);
                acc1b = fma2(qb.x, wh1[4 * k + 2], acc1b);
                acc1b = fma2(qb.y, wh1[4 * k + 3], acc1b);
            }
            // Packed reduction tree: 2 packed adds per output, 1 unpack, 1 add
            const u64 s0 = add2(acc0a, acc0b);
            const u64 s1 = add2(acc1a, acc1b);
            float f0l, f0h, f1l, f1h;
            unpack2(s0, f0l, f0h);
            unpack2(s1, f1l, f1h);
            const float h0 = tanh_fast(f0l + f0h);
            const float h1 = tanh_fast(f1l + f1h);

            const int nxt = cur ^ 1;
            reinterpret_cast<float2*>(hbuf[nxt][warp])[lane] =
                make_float2(h0, h1);
            __syncwarp();

            // Previous step's y-partial store (off the critical path)
            pbuf[warp][sp][lane] = yp_prev;
            yp_prev = fmaf(h0, wy0, h1 * wy1);
            sp = s;

            cur = nxt;
        }
        pbuf[warp][31][lane] = yp_prev;  // last step's partial
        __syncwarp();

        // y[t0+L] = sum over columns of pbuf[L][*] (stride-33: conflict-free)
        float r0 = 0.f, r1 = 0.f, r2 = 0.f, r3 = 0.f;
#pragma unroll
        for (int i = 0; i < 32; i += 4) {
            r0 += pbuf[warp][lane][i];
            r1 += pbuf[warp][lane][i + 1];
            r2 += pbuf[warp][lane][i + 2];
            r3 += pbuf[warp][lane][i + 3];
        }
        op[t0 + lane] = (r0 + r1) + (r2 + r3);
        __syncwarp();

        xv = xnext;
    }
}

extern "C" void kernel_launch(void* const* d_in, const int* in_sizes, int n_in,
                              void* d_out, int out_size) {
    const float* x_seq = (const float*)d_in[0];  // [1024, 2048, 1]
    const float* W_h   = (const float*)d_in[1];  // [64, 64]
    const float* W_x   = (const float*)d_in[2];  // [64, 1]
    const float* W_y   = (const float*)d_in[3];  // [1, 64]
    float* out = (float*)d_out;                  // [1024, 2048, 1]

    const int blocks = BB / WARPS_PER_CTA;  // 128
    rnn_dephase<<<blocks, THREADS>>>(x_seq, W_h, W_x, W_y, out);
}